// round 3
// baseline (speedup 1.0000x reference)
#include <cuda_runtime.h>
#include <cstdint>

// NoiseLinear: out[b,o] = sum_i x[b,i]*w[o,i] + bias[o]
//                       + 0.1 * sum_i eps[b,o,i]*w[o,i]*x[b,i]
// eps reproduced for JAX partitionable threefry (verified rel_err ~6e-7).
// R3: one batch row per warp (fewer regs), launch_bounds(256,6) for occupancy,
//     keep the ALU/FMA pipe split.

#define B_DIM  64
#define IN_DIM 1024
#define OUT_DIM 4096
#define NOISE_F 0.1f

// Opaque 1: loaded from memory so ptxas cannot strength-reduce IMAD -> IADD3.
__device__ unsigned int g_one = 1u;

// a + b forced onto the FMA pipe as IMAD (a*one + b).
#define MADD(d, a, b)                                                   \
    asm("mad.lo.u32 %0, %1, %2, %3;" : "=r"(d) : "r"(a), "r"(one), "r"(b))

struct TFK {
    uint32_t ks1, ks2, ks2p1, ks1p3, ks2p4, one;
};

__device__ __forceinline__ void tf2x32(const TFK& k, uint32_t basek, uint32_t i,
                                       uint32_t& o0, uint32_t& o1) {
    const uint32_t one = k.one;
    uint32_t x0, x1;
    MADD(x1, basek, i);        // counter + ks1  (basek = flat_base + ks1)
    x0 = x1;                   // round 1 add with x0_init = 0
    x1 = __funnelshift_l(x1, x1, 13); x1 ^= x0;
#define TF_R(r) { MADD(x0, x0, x1); x1 = __funnelshift_l(x1, x1, (r)); x1 ^= x0; }
    TF_R(15) TF_R(26) TF_R(6)
    MADD(x0, x0, k.ks1);  MADD(x1, x1, k.ks2p1);
    TF_R(17) TF_R(29) TF_R(16) TF_R(24)
    MADD(x0, x0, k.ks2);  x1 += 2u;            // + ks0(=0) + 2
    TF_R(13) TF_R(15) TF_R(26) TF_R(6)
    /* x0 += ks0 = 0 */   MADD(x1, x1, k.ks1p3);
    TF_R(17) TF_R(29) TF_R(16) TF_R(24)
    MADD(x0, x0, k.ks1);  MADD(x1, x1, k.ks2p4);
    TF_R(13) TF_R(15) TF_R(26) TF_R(6)
    MADD(x0, x0, k.ks2);  x1 += 5u;            // + ks0(=0) + 5
#undef TF_R
    o0 = x0; o1 = x1;
}

// bits -> N(0,1); sqrt(2) folded into the Giles polynomial coefficients.
__device__ __forceinline__ float bits_to_normal(uint32_t bits) {
    float v = __uint_as_float((bits >> 9) + 0x3f800000u);   // [1,2)
    float u = __fmaf_rn(v, 2.0f, -3.0f);                    // ~[-1,1)
    u = fmaxf(u, -0.99999994f);                             // keep 1-u^2 > 0
    float t = __fmaf_rn(u, -u, 1.0f);
    float w = __fmul_rn(__log2f(t), -0.69314718f);          // -log(1-u^2)
    float p;
    if (w < 5.0f) {
        w -= 2.5f;
        p = 3.9742549e-08f;
        p = __fmaf_rn(p, w, 4.8546651e-07f);
        p = __fmaf_rn(p, w, -4.9828354e-06f);
        p = __fmaf_rn(p, w, -6.2105158e-06f);
        p = __fmaf_rn(p, w, 3.0912028e-04f);
        p = __fmaf_rn(p, w, -1.7730373e-03f);
        p = __fmaf_rn(p, w, -5.9081330e-03f);
        p = __fmaf_rn(p, w, 3.4880532e-01f);
        p = __fmaf_rn(p, w, 2.1233136e+00f);
    } else {
        w = __fsqrt_rn(w) - 3.0f;
        p = -2.8314768e-04f;
        p = __fmaf_rn(p, w, 1.4276563e-04f);
        p = __fmaf_rn(p, w, 1.9082642e-03f);
        p = __fmaf_rn(p, w, -5.1950162e-03f);
        p = __fmaf_rn(p, w, 8.1168864e-03f);
        p = __fmaf_rn(p, w, -1.0779783e-02f);
        p = __fmaf_rn(p, w, 1.3348632e-02f);
        p = __fmaf_rn(p, w, 1.4165810e+00f);
        p = __fmaf_rn(p, w, 4.0064343e+00f);
    }
    return __fmul_rn(p, u);                                 // sqrt(2)*erfinv(u)
}

// One warp per (b, o). Lanes stride IN=1024 with float4 loads; 4 independent
// threefry chains per thread per iteration for ILP; butterfly reduce at end.
__global__ void __launch_bounds__(256, 6)
noise_linear_kernel(const float* __restrict__ x, const float* __restrict__ w,
                    const float* __restrict__ bias, const int* __restrict__ seedp,
                    float* __restrict__ out) {
    TFK k;
    k.one = *(volatile const unsigned int*)&g_one;   // opaque 1
    k.ks1 = (uint32_t)seedp[0];
    k.ks2 = k.ks1 ^ 0x1BD11BDAu;
    k.ks2p1 = k.ks2 + 1u;
    k.ks1p3 = k.ks1 + 3u;
    k.ks2p4 = k.ks2 + 4u;

    const int gw   = blockIdx.x * (blockDim.x >> 5) + (threadIdx.x >> 5);
    const int lane = threadIdx.x & 31;
    const int o = gw & (OUT_DIM - 1);
    const int b = gw >> 12;                          // 0..63

    const float4* __restrict__ wrow = (const float4*)(w + (size_t)o * IN_DIM);
    const float4* __restrict__ xrow = (const float4*)(x + (size_t)b * IN_DIM);

    // flat counter base = b*OUT*IN + o*IN  (< 2^28, fits u32); fold +ks1 in.
    const uint32_t bk = (uint32_t)b * (OUT_DIM * IN_DIM)
                      + (uint32_t)o * IN_DIM + k.ks1;

    float lin = 0.f, nacc = 0.f;

#pragma unroll 1
    for (int ii = 0; ii < IN_DIM / 128; ++ii) {      // 8 iterations
        const int vec = ii * 32 + lane;              // float4 index in the row
        const float4 w4 = __ldg(wrow + vec);
        const float4 x4 = __ldg(xrow + vec);
        const uint32_t ibase = (uint32_t)vec * 4u;
#pragma unroll
        for (int j = 0; j < 4; ++j) {
            const float t = __fmul_rn((&w4.x)[j], (&x4.x)[j]);
            lin = __fadd_rn(lin, t);

            uint32_t ra, rb;
            tf2x32(k, bk, ibase + (uint32_t)j, ra, rb);
            const float e = bits_to_normal(ra ^ rb);
            nacc = __fmaf_rn(e, t, nacc);
        }
    }

#pragma unroll
    for (int off = 16; off > 0; off >>= 1) {
        lin  += __shfl_xor_sync(0xFFFFFFFFu, lin,  off);
        nacc += __shfl_xor_sync(0xFFFFFFFFu, nacc, off);
    }

    if (lane == 0) {
        out[(size_t)b * OUT_DIM + o] = lin + __ldg(bias + o) + NOISE_F * nacc;
    }
}

extern "C" void kernel_launch(void* const* d_in, const int* in_sizes, int n_in,
                              void* d_out, int out_size) {
    const float* x    = (const float*)d_in[0];
    const float* w    = (const float*)d_in[1];
    const float* bias = (const float*)d_in[2];
    const int*   seed = (const int*)d_in[3];
    float* out = (float*)d_out;

    // 64 b * 4096 o = 262144 warps; 8 warps/block -> 32768 blocks
    noise_linear_kernel<<<32768, 256>>>(x, w, bias, seed, out);
}

// round 4
// speedup vs baseline: 1.1041x; 1.1041x over previous
#include <cuda_runtime.h>
#include <cstdint>

// NoiseLinear: out[b,o] = sum_i x[b,i]*w[o,i]*(1 + 0.1*eps[b,o,i]) + bias[o]
// eps = jax.random.normal(key(seed), (B,OUT,IN)) — partitionable threefry,
// verified bit-model (rel_err ~6e-7 in R1).
// R4: back to R1 structure (2 rows/warp, plain adds — ptxas auto-balances
// IMAD/IADD3); fused lin+noise accumulator; central Giles poly evaluated in
// log2-domain (coeffs pre-scaled by (-ln2)^k); warp-uniform rare-tail branch.

#define B_DIM  64
#define IN_DIM 1024
#define OUT_DIM 4096

__device__ __forceinline__ void tf2x32(uint32_t ks1, uint32_t ks2, uint32_t c1k,
                                       uint32_t& o0, uint32_t& o1) {
    // c1k = counter + ks1 (pre-added). x0_init = 0, so round-1 add is a move.
    uint32_t x0, x1 = c1k;
    x0 = x1;
    x1 = __funnelshift_l(x1, x1, 13); x1 ^= x0;
#define TF_R(r) { x0 += x1; x1 = __funnelshift_l(x1, x1, (r)); x1 ^= x0; }
    TF_R(15) TF_R(26) TF_R(6)
    x0 += ks1;      x1 += ks2 + 1u;
    TF_R(17) TF_R(29) TF_R(16) TF_R(24)
    x0 += ks2;      x1 += 2u;              // + ks0(=0) + 2
    TF_R(13) TF_R(15) TF_R(26) TF_R(6)
    /* x0 += ks0 */ x1 += ks1 + 3u;
    TF_R(17) TF_R(29) TF_R(16) TF_R(24)
    x0 += ks1;      x1 += ks2 + 4u;
    TF_R(13) TF_R(15) TF_R(26) TF_R(6)
    x0 += ks2;      x1 += 5u;              // + ks0(=0) + 5
#undef TF_R
    o0 = x0; o1 = x1;
}

// bits -> sqrt(2)*erfinv(u) with sqrt(2) folded into coefficients.
// Central branch evaluated directly in s = log2(1-u^2) + 2.5/ln2 domain:
// original Horner coeffs a_k (deg 8..0) scaled by (-ln2)^deg.
__device__ __forceinline__ float bits_to_normal(uint32_t bits) {
    float v = __uint_as_float((bits >> 9) + 0x3f800000u);   // [1,2)
    float u = __fmaf_rn(v, 2.0f, -3.0f);                    // ~[-1,1)
    u = fmaxf(u, -0.99999994f);                             // keep 1-u^2 > 0
    float t = __fmaf_rn(u, -u, 1.0f);                       // (0,1]
    float L = __log2f(t);                                   // <= 0
    // central poly: always computed. s = L + 2.5/ln2
    float s = __fadd_rn(L, 3.6067376f);
    float p;
    p = 2.1176117e-09f;
    p = __fmaf_rn(p, s, -3.7320261e-08f);
    p = __fmaf_rn(p, s, -5.5262276e-07f);
    p = __fmaf_rn(p, s, 9.9370005e-07f);
    p = __fmaf_rn(p, s, 7.1355326e-05f);
    p = __fmaf_rn(p, s, 5.9044926e-04f);
    p = __fmaf_rn(p, s, -2.8386012e-03f);
    p = __fmaf_rn(p, s, -2.4177344e-01f);
    p = __fmaf_rn(p, s, 2.1233136e+00f);
    // tail branch (w >= 5 <=> L <= -5/ln2): rare (~1.4% of lanes),
    // entered only when some lane in the warp needs it.
    if (__any_sync(0xFFFFFFFFu, L <= -7.2134752f)) {
        float w = __fmul_rn(L, -0.69314718f);
        float wq = __fsqrt_rn(w) - 3.0f;
        float q;
        q = -2.8314768e-04f;
        q = __fmaf_rn(q, wq, 1.4276563e-04f);
        q = __fmaf_rn(q, wq, 1.9082642e-03f);
        q = __fmaf_rn(q, wq, -5.1950162e-03f);
        q = __fmaf_rn(q, wq, 8.1168864e-03f);
        q = __fmaf_rn(q, wq, -1.0779783e-02f);
        q = __fmaf_rn(q, wq, 1.3348632e-02f);
        q = __fmaf_rn(q, wq, 1.4165810e+00f);
        q = __fmaf_rn(q, wq, 4.0064343e+00f);
        p = (L <= -7.2134752f) ? q : p;
    }
    return __fmul_rn(p, u);                                 // sqrt(2)*erfinv(u)
}

// One warp per (b-pair, o). b-pair = (bp, bp+32). Lanes stride IN=1024 with
// float4 loads; 8 independent threefry chains per loop body for ILP.
__global__ void __launch_bounds__(256, 4)
noise_linear_kernel(const float* __restrict__ x, const float* __restrict__ w,
                    const float* __restrict__ bias, const int* __restrict__ seedp,
                    float* __restrict__ out) {
    const uint32_t ks1 = (uint32_t)seedp[0];
    const uint32_t ks2 = ks1 ^ 0x1BD11BDAu;

    const int gw   = blockIdx.x * (blockDim.x >> 5) + (threadIdx.x >> 5);
    const int lane = threadIdx.x & 31;
    const int o  = gw & (OUT_DIM - 1);
    const int bp = gw >> 12;                 // 0..31
    const int b0 = bp, b1 = bp + 32;

    const float4* __restrict__ wrow  = (const float4*)(w + (size_t)o  * IN_DIM);
    const float4* __restrict__ x0row = (const float4*)(x + (size_t)b0 * IN_DIM);
    const float4* __restrict__ x1row = (const float4*)(x + (size_t)b1 * IN_DIM);

    // counter base + ks1 pre-folded
    const uint32_t bk0 = (uint32_t)b0 * (OUT_DIM * IN_DIM)
                       + (uint32_t)o * IN_DIM + ks1;
    const uint32_t bk1 = bk0 + 32u * (OUT_DIM * IN_DIM);

    float acc0 = 0.f, acc1 = 0.f;            // sum of t*(1 + 0.1*eps)

#pragma unroll 1
    for (int ii = 0; ii < IN_DIM / 128; ++ii) {     // 8 iterations
        const int vec = ii * 32 + lane;             // float4 index in the row
        const float4 w4 = __ldg(wrow  + vec);
        const float4 a4 = __ldg(x0row + vec);
        const float4 b4 = __ldg(x1row + vec);
        const uint32_t c0 = bk0 + (uint32_t)vec * 4u;   // per-iter counter base
        const uint32_t c1 = bk1 + (uint32_t)vec * 4u;
#pragma unroll
        for (int j = 0; j < 4; ++j) {
            const float wv = (&w4.x)[j];
            const float t0 = __fmul_rn(wv, (&a4.x)[j]);
            const float t1 = __fmul_rn(wv, (&b4.x)[j]);

            uint32_t r0a, r0b, r1a, r1b;
            tf2x32(ks1, ks2, c0 + (uint32_t)j, r0a, r0b);
            tf2x32(ks1, ks2, c1 + (uint32_t)j, r1a, r1b);
            const float e0 = bits_to_normal(r0a ^ r0b);
            const float e1 = bits_to_normal(r1a ^ r1b);

            const float m0 = __fmaf_rn(e0, 0.1f, 1.0f);
            const float m1 = __fmaf_rn(e1, 0.1f, 1.0f);
            acc0 = __fmaf_rn(m0, t0, acc0);
            acc1 = __fmaf_rn(m1, t1, acc1);
        }
    }

    // warp butterfly reduce (2 accumulators)
#pragma unroll
    for (int off = 16; off > 0; off >>= 1) {
        acc0 += __shfl_xor_sync(0xFFFFFFFFu, acc0, off);
        acc1 += __shfl_xor_sync(0xFFFFFFFFu, acc1, off);
    }

    if (lane == 0) {
        const float bz = __ldg(bias + o);
        out[(size_t)b0 * OUT_DIM + o] = acc0 + bz;
        out[(size_t)b1 * OUT_DIM + o] = acc1 + bz;
    }
}

extern "C" void kernel_launch(void* const* d_in, const int* in_sizes, int n_in,
                              void* d_out, int out_size) {
    const float* x    = (const float*)d_in[0];
    const float* w    = (const float*)d_in[1];
    const float* bias = (const float*)d_in[2];
    const int*   seed = (const int*)d_in[3];
    float* out = (float*)d_out;

    // 32 b-pairs * 4096 outputs = 131072 warps; 8 warps/block -> 16384 blocks
    noise_linear_kernel<<<16384, 256>>>(x, w, bias, seed, out);
}